// round 13
// baseline (speedup 1.0000x reference)
#include <cuda_runtime.h>
#include <cuda_fp16.h>

#define NN 100000
#define EMAX 3300000
#define H1D 4
#define CD 8
#define NEG 0.2f

#define NPB 2048          // nodes per bucket
#define NBKT 49           // ceil(NN / NPB)
#define BCTAS 256         // build blocks
#define BPB 6             // blocks per bucket in kE2B (49*6 = 294 = one wave @2/SM)

// Persistent device scratch (no allocations allowed in kernel_launch).
__device__ float g_ws[H1D];
__device__ float g_wd[H1D];
__device__ float g_acc1[NN * 8];    // per node: S0,T0,S1,T1,S2,T2,S3,T3 (32B aligned)
__device__ float g_acc2[NN * 12];   // per node: S, num[0..7], pad x3 (R4 layout)

// Packed layer-2 source record: h2 fp16x8 (16B) + als fp32 => 20B in 32B record
struct __align__(32) Node2 {
    __half2 h2[4];
    float   als;
    float   pad[3];
};
__device__ Node2 g_n2[NN];
__device__ float g_ald[NN];         // dense read-only (L1-cacheable)

// Bucketed edge structures
__device__ int g_cnt_pb[BCTAS * NBKT];
__device__ int g_base_pb[BCTAS * NBKT];
__device__ int g_bkt_tot[NBKT];
__device__ int g_bkt_start[NBKT];
__device__ unsigned int g_bp[EMAX];  // packed (src << 11) | local_dst

__device__ __forceinline__ void red4(float* addr, float a, float b, float c, float d) {
    asm volatile("red.global.add.v4.f32 [%0], {%1, %2, %3, %4};"
                 :: "l"(addr), "f"(a), "f"(b), "f"(c), "f"(d) : "memory");
}

// ---------------------------------------------------------------------------
// 1) zero accumulators + bucket totals + precompute per-head logit scalars
// ---------------------------------------------------------------------------
__global__ void k_zero_prep(const float* __restrict__ W1,
                            const float* __restrict__ as1,
                            const float* __restrict__ ad1) {
    int t = blockIdx.x * blockDim.x + threadIdx.x;
    int stride = gridDim.x * blockDim.x;
    float4 z = make_float4(0.f, 0.f, 0.f, 0.f);
    float4* a1 = reinterpret_cast<float4*>(g_acc1);   // NN*2 float4
    float4* a2 = reinterpret_cast<float4*>(g_acc2);   // NN*3 float4
    for (int i = t; i < NN * 3; i += stride) {
        a2[i] = z;
        if (i < NN * 2) a1[i] = z;
    }
    if (t < NBKT) g_bkt_tot[t] = 0;
    if (t >= 64 && t < 64 + H1D) {
        int h = t - 64;
        float s = 0.0f, d = 0.0f;
#pragma unroll
        for (int c = 0; c < CD; c++) {
            float w = W1[h * CD + c];
            s += w * as1[h * CD + c];
            d += w * ad1[h * CD + c];
        }
        g_ws[h] = s;
        g_wd[h] = d;
    }
}

// ---------------------------------------------------------------------------
// Build 1: per-block per-bucket counts (SMEM histogram)
// ---------------------------------------------------------------------------
__global__ void __launch_bounds__(256) kB1(const int* __restrict__ dst, int E) {
    __shared__ int sh[NBKT];
    int tid = threadIdx.x;
    if (tid < NBKT) sh[tid] = 0;
    __syncthreads();
    int chunk = (E + BCTAS - 1) / BCTAS;
    int lo = blockIdx.x * chunk;
    int hi = min(E, lo + chunk);
    for (int i = lo + tid; i < hi; i += 256)
        atomicAdd(&sh[dst[i] >> 11], 1);
    __syncthreads();
    if (tid < NBKT) {
        g_cnt_pb[blockIdx.x * NBKT + tid] = sh[tid];
        atomicAdd(&g_bkt_tot[tid], sh[tid]);
    }
}

// ---------------------------------------------------------------------------
// Build 2a: bucket region starts (serial scan over 49 in SMEM)
// ---------------------------------------------------------------------------
__global__ void kB2a() {
    __shared__ int st[NBKT];
    int t = threadIdx.x;
    if (t < NBKT) st[t] = g_bkt_tot[t];
    __syncthreads();
    if (t == 0) {
        int run = 0;
        for (int b = 0; b < NBKT; b++) { g_bkt_start[b] = run; run += st[b]; }
    }
}

// ---------------------------------------------------------------------------
// Build 2b: per-bucket exclusive scan over the 256 block counts
// ---------------------------------------------------------------------------
__global__ void __launch_bounds__(256) kB2b() {
    __shared__ int sh[BCTAS];
    int t = threadIdx.x;
    int b = blockIdx.x;
    int v = g_cnt_pb[t * NBKT + b];
    sh[t] = v;
    __syncthreads();
    for (int o = 1; o < BCTAS; o <<= 1) {
        int a = (t >= o) ? sh[t - o] : 0;
        __syncthreads();
        sh[t] += a;
        __syncthreads();
    }
    g_base_pb[t * NBKT + b] = g_bkt_start[b] + sh[t] - v;
}

// ---------------------------------------------------------------------------
// Build 3: scatter packed edges into bucket regions (SMEM cursors)
// ---------------------------------------------------------------------------
__global__ void __launch_bounds__(256) kB3(const int* __restrict__ src,
                                           const int* __restrict__ dst, int E) {
    __shared__ int cur[NBKT];
    int tid = threadIdx.x;
    if (tid < NBKT) cur[tid] = g_base_pb[blockIdx.x * NBKT + tid];
    __syncthreads();
    int chunk = (E + BCTAS - 1) / BCTAS;
    int lo = blockIdx.x * chunk;
    int hi = min(E, lo + chunk);
    for (int i = lo + tid; i < hi; i += 256) {
        int d = dst[i];
        int s = src[i];
        int bkt = d >> 11;
        int slot = atomicAdd(&cur[bkt], 1);
        g_bp[slot] = ((unsigned)s << 11) | (unsigned)(d & 2047);
    }
}

// ---------------------------------------------------------------------------
// 2) layer-1 edge pass (unchanged R11 path): 2 edges/thread, global v4 REDs
// ---------------------------------------------------------------------------
__device__ __forceinline__ void edge1_body(const float* __restrict__ x, int s, int d) {
    float xs = __ldg(&x[s]);
    float xd = __ldg(&x[d]);
    float v[8];
#pragma unroll
    for (int h = 0; h < H1D; h++) {
        float e = xs * g_ws[h] + xd * g_wd[h];
        e = (e > 0.0f) ? e : NEG * e;
        float w = __expf(e);
        v[2 * h]     = w;
        v[2 * h + 1] = w * xs;
    }
    float* base = &g_acc1[(size_t)d * 8];
    red4(base,     v[0], v[1], v[2], v[3]);
    red4(base + 4, v[4], v[5], v[6], v[7]);
}

__global__ void __launch_bounds__(256) k_edge1(const float* __restrict__ x,
                                               const int* __restrict__ src,
                                               const int* __restrict__ dst,
                                               int E) {
    int t = blockIdx.x * blockDim.x + threadIdx.x;
    int i0 = 2 * t;
    if (i0 >= E) return;
    if (i0 + 1 < E) {
        int2 ss = *reinterpret_cast<const int2*>(src + i0);
        int2 dd = *reinterpret_cast<const int2*>(dst + i0);
        edge1_body(x, ss.x, dd.x);
        edge1_body(x, ss.y, dd.y);
    } else {
        edge1_body(x, src[i0], dst[i0]);
    }
}

// ---------------------------------------------------------------------------
// 3) per-node: layer-1 self-loop + epilogue + relu + W2 GEMV + logits
// ---------------------------------------------------------------------------
__global__ void __launch_bounds__(256) k_mid(const float* __restrict__ x,
                                             const float* __restrict__ W1,
                                             const float* __restrict__ b1,
                                             const float* __restrict__ W2,
                                             const float* __restrict__ as2,
                                             const float* __restrict__ ad2) {
    __shared__ float sW2[32 * 8];
    __shared__ float sW1[32];
    __shared__ float sb1[32];
    __shared__ float sa[16];
    int tid = threadIdx.x;
    if (tid < 256) sW2[tid] = W2[tid];
    if (tid < 32) { sW1[tid] = W1[tid]; sb1[tid] = b1[tid]; }
    if (tid < 8)  { sa[tid] = as2[tid]; sa[8 + tid] = ad2[tid]; }
    __syncthreads();

    int n = blockIdx.x * blockDim.x + tid;
    if (n >= NN) return;

    const float4* a1 = reinterpret_cast<const float4*>(&g_acc1[(size_t)n * 8]);
    float4 p0 = a1[0];
    float4 p1 = a1[1];

    float xd = __ldg(&x[n]);
    float Sv[H1D] = {p0.x, p0.z, p1.x, p1.z};
    float Tv[H1D] = {p0.y, p0.w, p1.y, p1.w};
#pragma unroll
    for (int h = 0; h < H1D; h++) {
        float e = xd * (g_ws[h] + g_wd[h]);
        e = (e > 0.0f) ? e : NEG * e;
        float w = __expf(e);
        Sv[h] += w;
        Tv[h] += w * xd;
    }

    float ts[H1D];
#pragma unroll
    for (int h = 0; h < H1D; h++) ts[h] = Tv[h] / Sv[h];

    float h2[CD];
#pragma unroll
    for (int c = 0; c < CD; c++) h2[c] = 0.0f;
#pragma unroll
    for (int hc = 0; hc < 32; hc++) {
        float r = sW1[hc] * ts[hc >> 3] + sb1[hc];
        r = fmaxf(r, 0.0f);
#pragma unroll
        for (int c = 0; c < CD; c++) h2[c] += r * sW2[hc * 8 + c];
    }
    float als = 0.0f, ald = 0.0f;
#pragma unroll
    for (int c = 0; c < CD; c++) {
        als += h2[c] * sa[c];
        ald += h2[c] * sa[8 + c];
    }

    __half2 pk[4];
    pk[0] = __floats2half2_rn(h2[0], h2[1]);
    pk[1] = __floats2half2_rn(h2[2], h2[3]);
    pk[2] = __floats2half2_rn(h2[4], h2[5]);
    pk[3] = __floats2half2_rn(h2[6], h2[7]);
    *reinterpret_cast<uint4*>(g_n2[n].h2) = *reinterpret_cast<const uint4*>(pk);
    g_n2[n].als = als;
    g_ald[n] = ald;
}

// ---------------------------------------------------------------------------
// 4) bucketed layer-2 pass: SMEM fp32 accumulation, then merge partials
// ---------------------------------------------------------------------------
__global__ void __launch_bounds__(256) kE2B() {
    extern __shared__ float sm[];
    float* sacc = sm;               // NPB * 10 (stride 10 to spread banks)
    float* sald = sm + NPB * 10;    // NPB
    int tid = threadIdx.x;
    int bkt = blockIdx.x / BPB;
    int sub = blockIdx.x % BPB;
    int nbase = bkt * NPB;
    int nloc = min(NPB, NN - nbase);

    for (int i = tid; i < NPB * 10; i += 256) sacc[i] = 0.0f;
    for (int i = tid; i < nloc; i += 256) sald[i] = g_ald[nbase + i];
    __syncthreads();

    int bstart = g_bkt_start[bkt];
    int tot = g_bkt_tot[bkt];
    int est = bstart + (int)((long long)tot * sub / BPB);
    int een = bstart + (int)((long long)tot * (sub + 1) / BPB);

    for (int i = est + tid; i < een; i += 256) {
        unsigned v = __ldg(&g_bp[i]);
        int loc = v & 2047u;
        int s = v >> 11;
        uint4 raw = *reinterpret_cast<const uint4*>(g_n2[s].h2);
        __half2 pk[4];
        *reinterpret_cast<uint4*>(pk) = raw;
        float als = g_n2[s].als;

        float e = als + sald[loc];
        e = (e > 0.0f) ? e : NEG * e;
        float w = __expf(e);

        float2 f0 = __half22float2(pk[0]);
        float2 f1 = __half22float2(pk[1]);
        float2 f2 = __half22float2(pk[2]);
        float2 f3 = __half22float2(pk[3]);

        float* a = &sacc[loc * 10];
        atomicAdd(a + 0, w);
        atomicAdd(a + 1, w * f0.x);
        atomicAdd(a + 2, w * f0.y);
        atomicAdd(a + 3, w * f1.x);
        atomicAdd(a + 4, w * f1.y);
        atomicAdd(a + 5, w * f2.x);
        atomicAdd(a + 6, w * f2.y);
        atomicAdd(a + 7, w * f3.x);
        atomicAdd(a + 8, w * f3.y);
    }
    __syncthreads();

    // merge this block's partials into g_acc2 (R4 layout)
    for (int j = tid; j < nloc; j += 256) {
        float* a = &sacc[j * 10];
        float S = a[0];
        if (S != 0.0f) {
            float* ab = &g_acc2[(size_t)(nbase + j) * 12];
            red4(ab,     S,    a[1], a[2], a[3]);
            red4(ab + 4, a[4], a[5], a[6], a[7]);
            atomicAdd(ab + 8, a[8]);
        }
    }
}

// ---------------------------------------------------------------------------
// 5) final: add layer-2 self-loop analytically, normalize + bias -> out
// ---------------------------------------------------------------------------
__global__ void __launch_bounds__(256) k_final(float* __restrict__ out,
                                               const float* __restrict__ b2) {
    __shared__ float sb2[8];
    int tid = threadIdx.x;
    if (tid < 8) sb2[tid] = b2[tid];
    __syncthreads();

    int n = blockIdx.x * blockDim.x + tid;
    if (n >= NN) return;

    const float* ab = &g_acc2[(size_t)n * 12];
    float S  = ab[0];
    float4 q0 = make_float4(ab[1], ab[2], ab[3], ab[4]);
    float4 q1 = make_float4(ab[5], ab[6], ab[7], ab[8]);

    uint4 raw = *reinterpret_cast<const uint4*>(g_n2[n].h2);
    __half2 pk[4];
    *reinterpret_cast<uint4*>(pk) = raw;
    float als = g_n2[n].als;
    float ald = g_ald[n];

    float e = als + ald;
    e = (e > 0.0f) ? e : NEG * e;
    float w = __expf(e);

    float2 f0 = __half22float2(pk[0]);
    float2 f1 = __half22float2(pk[1]);
    float2 f2 = __half22float2(pk[2]);
    float2 f3 = __half22float2(pk[3]);

    float inv = 1.0f / (S + w);
    float4 o0 = make_float4((q0.x + w * f0.x) * inv + sb2[0],
                            (q0.y + w * f0.y) * inv + sb2[1],
                            (q0.z + w * f1.x) * inv + sb2[2],
                            (q0.w + w * f1.y) * inv + sb2[3]);
    float4 o1 = make_float4((q1.x + w * f2.x) * inv + sb2[4],
                            (q1.y + w * f2.y) * inv + sb2[5],
                            (q1.z + w * f3.x) * inv + sb2[6],
                            (q1.w + w * f3.y) * inv + sb2[7]);
    float4* ob = reinterpret_cast<float4*>(&out[(size_t)n * 8]);
    ob[0] = o0;
    ob[1] = o1;
}

extern "C" void kernel_launch(void* const* d_in, const int* in_sizes, int n_in,
                              void* d_out, int out_size) {
    const float* x   = (const float*)d_in[0];
    const int*   ei  = (const int*)d_in[1];
    const float* W1  = (const float*)d_in[2];
    const float* as1 = (const float*)d_in[3];
    const float* ad1 = (const float*)d_in[4];
    const float* b1  = (const float*)d_in[5];
    const float* W2  = (const float*)d_in[6];
    const float* as2 = (const float*)d_in[7];
    const float* ad2 = (const float*)d_in[8];
    const float* b2  = (const float*)d_in[9];
    float* out = (float*)d_out;

    int E = in_sizes[1] / 2;
    const int* src = ei;
    const int* dst = ei + E;

    int tb = 256;
    int eb2 = ((E + 1) / 2 + tb - 1) / tb;
    int nb = (NN + tb - 1) / tb;
    int smem_e2b = (NPB * 10 + NPB) * sizeof(float);  // 90112 B

    static int attr_done = 0;
    cudaFuncSetAttribute(kE2B, cudaFuncAttributeMaxDynamicSharedMemorySize, smem_e2b);
    (void)attr_done;

    k_zero_prep<<<1024, tb>>>(W1, as1, ad1);
    kB1<<<BCTAS, tb>>>(dst, E);
    kB2a<<<1, 64>>>();
    kB2b<<<NBKT, tb>>>();
    kB3<<<BCTAS, tb>>>(src, dst, E);
    k_edge1<<<eb2, tb>>>(x, src, dst, E);
    k_mid<<<nb, tb>>>(x, W1, b1, W2, as2, ad2);
    kE2B<<<NBKT * BPB, tb, smem_e2b>>>();
    k_final<<<nb, tb>>>(out, b2);
}

// round 14
// speedup vs baseline: 1.2575x; 1.2575x over previous
#include <cuda_runtime.h>
#include <cuda_fp16.h>

#define NN 100000
#define H1D 4
#define CD 8
#define NEG 0.2f

// Persistent device scratch (no allocations allowed in kernel_launch).
__device__ float g_ws[H1D];
__device__ float g_wd[H1D];
__device__ float g_acc1[NN * 8];    // per node: S0,T0,S1,T1,S2,T2,S3,T3 (32B aligned)
__device__ float g_acc2[NN * 12];   // per node: S, num[0..7], pad x3 (R4 layout)

// Packed layer-2 source record: h2 fp16x8 (16B) + als fp32 => 20B in 32B record
struct __align__(32) Node2 {
    __half2 h2[4];
    float   als;
    float   pad[3];
};
__device__ Node2 g_n2[NN];
__device__ float g_ald[NN];         // dense read-only during edge2 (L1-cacheable)

__device__ __forceinline__ void red4(float* addr, float a, float b, float c, float d) {
    asm volatile("red.global.add.v4.f32 [%0], {%1, %2, %3, %4};"
                 :: "l"(addr), "f"(a), "f"(b), "f"(c), "f"(d) : "memory");
}

// ---------------------------------------------------------------------------
// 1) zero layer-1 accumulators + precompute per-head logit scalars
//    (g_acc2 is initialized lazily by k_mid)
// ---------------------------------------------------------------------------
__global__ void k_zero_prep(const float* __restrict__ W1,
                            const float* __restrict__ as1,
                            const float* __restrict__ ad1) {
    int t = blockIdx.x * blockDim.x + threadIdx.x;
    int stride = gridDim.x * blockDim.x;
    float4 z = make_float4(0.f, 0.f, 0.f, 0.f);
    float4* a1 = reinterpret_cast<float4*>(g_acc1);   // NN*2 float4
    for (int i = t; i < NN * 2; i += stride) a1[i] = z;
    if (t < H1D) {
        float s = 0.0f, d = 0.0f;
#pragma unroll
        for (int c = 0; c < CD; c++) {
            float w = W1[t * CD + c];
            s += w * as1[t * CD + c];
            d += w * ad1[t * CD + c];
        }
        g_ws[t] = s;
        g_wd[t] = d;
    }
}

// ---------------------------------------------------------------------------
// 2) layer-1 edge pass (real edges only), 4 edges per thread (int4 indices):
//    per head: w = exp(lrelu(x_s*ws + x_d*wd)); acc1[dst] += {S_h: w, T_h: w*x_s}
// ---------------------------------------------------------------------------
__device__ __forceinline__ void edge1_body(const float* __restrict__ x, int s, int d) {
    float xs = __ldg(&x[s]);
    float xd = __ldg(&x[d]);
    float v[8];
#pragma unroll
    for (int h = 0; h < H1D; h++) {
        float e = xs * g_ws[h] + xd * g_wd[h];
        e = (e > 0.0f) ? e : NEG * e;
        float w = __expf(e);
        v[2 * h]     = w;
        v[2 * h + 1] = w * xs;
    }
    float* base = &g_acc1[(size_t)d * 8];
    red4(base,     v[0], v[1], v[2], v[3]);
    red4(base + 4, v[4], v[5], v[6], v[7]);
}

__global__ void __launch_bounds__(256) k_edge1(const float* __restrict__ x,
                                               const int* __restrict__ src,
                                               const int* __restrict__ dst,
                                               int E) {
    int t = blockIdx.x * blockDim.x + threadIdx.x;
    int i0 = 4 * t;
    if (i0 + 3 < E) {
        int4 ss = *reinterpret_cast<const int4*>(src + i0);
        int4 dd = *reinterpret_cast<const int4*>(dst + i0);
        edge1_body(x, ss.x, dd.x);
        edge1_body(x, ss.y, dd.y);
        edge1_body(x, ss.z, dd.z);
        edge1_body(x, ss.w, dd.w);
    } else {
        for (int i = i0; i < E; i++) edge1_body(x, src[i], dst[i]);
    }
}

// ---------------------------------------------------------------------------
// 3) per-node: layer-1 self-loop + epilogue + relu + W2 GEMV + layer-2 logit
//    precompute. Writes packed source record + dense ald + zero-inits g_acc2.
// ---------------------------------------------------------------------------
__global__ void __launch_bounds__(256) k_mid(const float* __restrict__ x,
                                             const float* __restrict__ W1,
                                             const float* __restrict__ b1,
                                             const float* __restrict__ W2,
                                             const float* __restrict__ as2,
                                             const float* __restrict__ ad2) {
    __shared__ float sW2[32 * 8];
    __shared__ float sW1[32];
    __shared__ float sb1[32];
    __shared__ float sa[16];
    int tid = threadIdx.x;
    if (tid < 256) sW2[tid] = W2[tid];
    if (tid < 32) { sW1[tid] = W1[tid]; sb1[tid] = b1[tid]; }
    if (tid < 8)  { sa[tid] = as2[tid]; sa[8 + tid] = ad2[tid]; }
    __syncthreads();

    int n = blockIdx.x * blockDim.x + tid;
    if (n >= NN) return;

    const float4* a1 = reinterpret_cast<const float4*>(&g_acc1[(size_t)n * 8]);
    float4 p0 = a1[0];  // S0,T0,S1,T1
    float4 p1 = a1[1];  // S2,T2,S3,T3

    // layer-1 self-loop contribution (src = dst = n)
    float xd = __ldg(&x[n]);
    float Sv[H1D] = {p0.x, p0.z, p1.x, p1.z};
    float Tv[H1D] = {p0.y, p0.w, p1.y, p1.w};
#pragma unroll
    for (int h = 0; h < H1D; h++) {
        float e = xd * (g_ws[h] + g_wd[h]);
        e = (e > 0.0f) ? e : NEG * e;
        float w = __expf(e);
        Sv[h] += w;
        Tv[h] += w * xd;
    }

    float ts[H1D];
#pragma unroll
    for (int h = 0; h < H1D; h++) ts[h] = Tv[h] / Sv[h];

    float h2[CD];
#pragma unroll
    for (int c = 0; c < CD; c++) h2[c] = 0.0f;
#pragma unroll
    for (int hc = 0; hc < 32; hc++) {
        float r = sW1[hc] * ts[hc >> 3] + sb1[hc];
        r = fmaxf(r, 0.0f);
#pragma unroll
        for (int c = 0; c < CD; c++) h2[c] += r * sW2[hc * 8 + c];
    }
    float als = 0.0f, ald = 0.0f;
#pragma unroll
    for (int c = 0; c < CD; c++) {
        als += h2[c] * sa[c];
        ald += h2[c] * sa[8 + c];
    }

    // pack h2 -> fp16x8 (one 16B store) + als
    __half2 pk[4];
    pk[0] = __floats2half2_rn(h2[0], h2[1]);
    pk[1] = __floats2half2_rn(h2[2], h2[3]);
    pk[2] = __floats2half2_rn(h2[4], h2[5]);
    pk[3] = __floats2half2_rn(h2[6], h2[7]);
    *reinterpret_cast<uint4*>(g_n2[n].h2) = *reinterpret_cast<const uint4*>(pk);
    g_n2[n].als = als;
    g_ald[n] = ald;

    // lazy zero-init of this node's layer-2 accumulator record (used by edge2)
    float* ab = &g_acc2[(size_t)n * 12];
    float4 z = make_float4(0.f, 0.f, 0.f, 0.f);
    reinterpret_cast<float4*>(ab)[0] = z;
    reinterpret_cast<float4*>(ab)[1] = z;
    ab[8] = 0.0f;
}

// ---------------------------------------------------------------------------
// 4) layer-2 edge pass (real edges only), 4 edges per thread (int4 indices):
//    w = exp(lrelu(als[s] + ald[d])); acc2[d] += {S: w, num[c]: w*h2[s][c]}
// ---------------------------------------------------------------------------
__device__ __forceinline__ void edge2_body(int s, int d) {
    uint4 raw = *reinterpret_cast<const uint4*>(g_n2[s].h2);
    __half2 pk[4];
    *reinterpret_cast<uint4*>(pk) = raw;
    float als = g_n2[s].als;
    float ald = __ldg(&g_ald[d]);

    float e = als + ald;
    e = (e > 0.0f) ? e : NEG * e;
    float w = __expf(e);

    float2 f0 = __half22float2(pk[0]);
    float2 f1 = __half22float2(pk[1]);
    float2 f2 = __half22float2(pk[2]);
    float2 f3 = __half22float2(pk[3]);

    float* ab = &g_acc2[(size_t)d * 12];
    red4(ab,     w,        w * f0.x, w * f0.y, w * f1.x);
    red4(ab + 4, w * f1.y, w * f2.x, w * f2.y, w * f3.x);
    atomicAdd(ab + 8, w * f3.y);
}

__global__ void __launch_bounds__(256) k_edge2(const int* __restrict__ src,
                                               const int* __restrict__ dst,
                                               int E) {
    int t = blockIdx.x * blockDim.x + threadIdx.x;
    int i0 = 4 * t;
    if (i0 + 3 < E) {
        int4 ss = *reinterpret_cast<const int4*>(src + i0);
        int4 dd = *reinterpret_cast<const int4*>(dst + i0);
        edge2_body(ss.x, dd.x);
        edge2_body(ss.y, dd.y);
        edge2_body(ss.z, dd.z);
        edge2_body(ss.w, dd.w);
    } else {
        for (int i = i0; i < E; i++) edge2_body(src[i], dst[i]);
    }
}

// ---------------------------------------------------------------------------
// 5) final: add layer-2 self-loop analytically, normalize + bias -> out
// ---------------------------------------------------------------------------
__global__ void __launch_bounds__(256) k_final(float* __restrict__ out,
                                               const float* __restrict__ b2) {
    __shared__ float sb2[8];
    int tid = threadIdx.x;
    if (tid < 8) sb2[tid] = b2[tid];
    __syncthreads();

    int n = blockIdx.x * blockDim.x + tid;
    if (n >= NN) return;

    const float* ab = &g_acc2[(size_t)n * 12];
    float S  = ab[0];
    float4 q0 = make_float4(ab[1], ab[2], ab[3], ab[4]);
    float4 q1 = make_float4(ab[5], ab[6], ab[7], ab[8]);

    // layer-2 self-loop from own record
    uint4 raw = *reinterpret_cast<const uint4*>(g_n2[n].h2);
    __half2 pk[4];
    *reinterpret_cast<uint4*>(pk) = raw;
    float als = g_n2[n].als;
    float ald = g_ald[n];

    float e = als + ald;
    e = (e > 0.0f) ? e : NEG * e;
    float w = __expf(e);

    float2 f0 = __half22float2(pk[0]);
    float2 f1 = __half22float2(pk[1]);
    float2 f2 = __half22float2(pk[2]);
    float2 f3 = __half22float2(pk[3]);

    float inv = 1.0f / (S + w);
    float4 o0 = make_float4((q0.x + w * f0.x) * inv + sb2[0],
                            (q0.y + w * f0.y) * inv + sb2[1],
                            (q0.z + w * f1.x) * inv + sb2[2],
                            (q0.w + w * f1.y) * inv + sb2[3]);
    float4 o1 = make_float4((q1.x + w * f2.x) * inv + sb2[4],
                            (q1.y + w * f2.y) * inv + sb2[5],
                            (q1.z + w * f3.x) * inv + sb2[6],
                            (q1.w + w * f3.y) * inv + sb2[7]);
    float4* ob = reinterpret_cast<float4*>(&out[(size_t)n * 8]);
    ob[0] = o0;
    ob[1] = o1;
}

extern "C" void kernel_launch(void* const* d_in, const int* in_sizes, int n_in,
                              void* d_out, int out_size) {
    const float* x   = (const float*)d_in[0];
    const int*   ei  = (const int*)d_in[1];
    const float* W1  = (const float*)d_in[2];
    const float* as1 = (const float*)d_in[3];
    const float* ad1 = (const float*)d_in[4];
    const float* b1  = (const float*)d_in[5];
    const float* W2  = (const float*)d_in[6];
    const float* as2 = (const float*)d_in[7];
    const float* ad2 = (const float*)d_in[8];
    const float* b2  = (const float*)d_in[9];
    float* out = (float*)d_out;

    int E = in_sizes[1] / 2;
    const int* src = ei;
    const int* dst = ei + E;

    int tb = 256;
    int eb4 = ((E + 3) / 4 + tb - 1) / tb;   // 4 edges per thread
    int nb = (NN + tb - 1) / tb;

    k_zero_prep<<<512, tb>>>(W1, as1, ad1);
    k_edge1<<<eb4, tb>>>(x, src, dst, E);
    k_mid<<<nb, tb>>>(x, W1, b1, W2, as2, ad2);
    k_edge2<<<eb4, tb>>>(src, dst, E);
    k_final<<<nb, tb>>>(out, b2);
}

// round 15
// speedup vs baseline: 1.2785x; 1.0167x over previous
#include <cuda_runtime.h>
#include <cuda_fp16.h>

#define NN 100000
#define H1D 4
#define CD 8
#define NEG 0.2f

// Persistent device scratch (no allocations allowed in kernel_launch).
// Zero-initialized at module load; k_final restores g_acc1's zero invariant,
// k_mid lazily initializes g_acc2 each call.
__device__ float g_acc1[NN * 8];    // per node: S0,T0,S1,T1,S2,T2,S3,T3 (32B aligned)
__device__ float g_acc2[NN * 12];   // per node: S, num[0..7], pad x3

// Packed layer-2 source record: h2 fp16x8 (16B) + als fp32 => 20B in 32B record
struct __align__(32) Node2 {
    __half2 h2[4];
    float   als;
    float   pad[3];
};
__device__ Node2 g_n2[NN];
__device__ float g_ald[NN];         // dense read-only during edge2 (L1-cacheable)

__device__ __forceinline__ void red4(float* addr, float a, float b, float c, float d) {
    asm volatile("red.global.add.v4.f32 [%0], {%1, %2, %3, %4};"
                 :: "l"(addr), "f"(a), "f"(b), "f"(c), "f"(d) : "memory");
}

// Compute per-head logit scalars ws/wd into shared memory (threads 0..3).
__device__ __forceinline__ void prep_wswd(float* sws, float* swd,
                                          const float* __restrict__ W1,
                                          const float* __restrict__ as1,
                                          const float* __restrict__ ad1) {
    int tid = threadIdx.x;
    if (tid < H1D) {
        float s = 0.0f, d = 0.0f;
#pragma unroll
        for (int c = 0; c < CD; c++) {
            float w = W1[tid * CD + c];
            s += w * as1[tid * CD + c];
            d += w * ad1[tid * CD + c];
        }
        sws[tid] = s;
        swd[tid] = d;
    }
}

// ---------------------------------------------------------------------------
// 1) layer-1 edge pass (real edges only), 2 edges per thread (int2 indices):
//    per head: w = exp(lrelu(x_s*ws + x_d*wd)); acc1[dst] += {S_h: w, T_h: w*x_s}
// ---------------------------------------------------------------------------
__device__ __forceinline__ void edge1_body(const float* __restrict__ x,
                                           const float* sws, const float* swd,
                                           int s, int d) {
    float xs = __ldg(&x[s]);
    float xd = __ldg(&x[d]);
    float v[8];
#pragma unroll
    for (int h = 0; h < H1D; h++) {
        float e = xs * sws[h] + xd * swd[h];
        e = (e > 0.0f) ? e : NEG * e;
        float w = __expf(e);
        v[2 * h]     = w;
        v[2 * h + 1] = w * xs;
    }
    float* base = &g_acc1[(size_t)d * 8];
    red4(base,     v[0], v[1], v[2], v[3]);
    red4(base + 4, v[4], v[5], v[6], v[7]);
}

__global__ void __launch_bounds__(256) k_edge1(const float* __restrict__ x,
                                               const int* __restrict__ src,
                                               const int* __restrict__ dst,
                                               const float* __restrict__ W1,
                                               const float* __restrict__ as1,
                                               const float* __restrict__ ad1,
                                               int E) {
    __shared__ float sws[H1D], swd[H1D];
    prep_wswd(sws, swd, W1, as1, ad1);
    __syncthreads();

    int t = blockIdx.x * blockDim.x + threadIdx.x;
    int i0 = 2 * t;
    if (i0 >= E) return;
    if (i0 + 1 < E) {
        int2 ss = *reinterpret_cast<const int2*>(src + i0);
        int2 dd = *reinterpret_cast<const int2*>(dst + i0);
        edge1_body(x, sws, swd, ss.x, dd.x);
        edge1_body(x, sws, swd, ss.y, dd.y);
    } else {
        edge1_body(x, sws, swd, src[i0], dst[i0]);
    }
}

// ---------------------------------------------------------------------------
// 2) per-node: layer-1 self-loop + epilogue + relu + W2 GEMV + layer-2 logit
//    precompute. Writes packed source record + dense ald + zero-inits g_acc2.
// ---------------------------------------------------------------------------
__global__ void __launch_bounds__(256) k_mid(const float* __restrict__ x,
                                             const float* __restrict__ W1,
                                             const float* __restrict__ as1,
                                             const float* __restrict__ ad1,
                                             const float* __restrict__ b1,
                                             const float* __restrict__ W2,
                                             const float* __restrict__ as2,
                                             const float* __restrict__ ad2) {
    __shared__ float sW2[32 * 8];
    __shared__ float sW1[32];
    __shared__ float sb1[32];
    __shared__ float sa[16];
    __shared__ float sws[H1D], swd[H1D];
    int tid = threadIdx.x;
    prep_wswd(sws, swd, W1, as1, ad1);
    if (tid < 256) sW2[tid] = W2[tid];
    if (tid < 32) { sW1[tid] = W1[tid]; sb1[tid] = b1[tid]; }
    if (tid < 8)  { sa[tid] = as2[tid]; sa[8 + tid] = ad2[tid]; }
    __syncthreads();

    int n = blockIdx.x * blockDim.x + tid;
    if (n >= NN) return;

    const float4* a1 = reinterpret_cast<const float4*>(&g_acc1[(size_t)n * 8]);
    float4 p0 = a1[0];  // S0,T0,S1,T1
    float4 p1 = a1[1];  // S2,T2,S3,T3

    // layer-1 self-loop contribution (src = dst = n)
    float xd = __ldg(&x[n]);
    float Sv[H1D] = {p0.x, p0.z, p1.x, p1.z};
    float Tv[H1D] = {p0.y, p0.w, p1.y, p1.w};
#pragma unroll
    for (int h = 0; h < H1D; h++) {
        float e = xd * (sws[h] + swd[h]);
        e = (e > 0.0f) ? e : NEG * e;
        float w = __expf(e);
        Sv[h] += w;
        Tv[h] += w * xd;
    }

    float ts[H1D];
#pragma unroll
    for (int h = 0; h < H1D; h++) ts[h] = Tv[h] / Sv[h];

    float h2[CD];
#pragma unroll
    for (int c = 0; c < CD; c++) h2[c] = 0.0f;
#pragma unroll
    for (int hc = 0; hc < 32; hc++) {
        float r = sW1[hc] * ts[hc >> 3] + sb1[hc];
        r = fmaxf(r, 0.0f);
#pragma unroll
        for (int c = 0; c < CD; c++) h2[c] += r * sW2[hc * 8 + c];
    }
    float als = 0.0f, ald = 0.0f;
#pragma unroll
    for (int c = 0; c < CD; c++) {
        als += h2[c] * sa[c];
        ald += h2[c] * sa[8 + c];
    }

    // pack h2 -> fp16x8 (one 16B store) + als
    __half2 pk[4];
    pk[0] = __floats2half2_rn(h2[0], h2[1]);
    pk[1] = __floats2half2_rn(h2[2], h2[3]);
    pk[2] = __floats2half2_rn(h2[4], h2[5]);
    pk[3] = __floats2half2_rn(h2[6], h2[7]);
    *reinterpret_cast<uint4*>(g_n2[n].h2) = *reinterpret_cast<const uint4*>(pk);
    g_n2[n].als = als;
    g_ald[n] = ald;

    // lazy zero-init of this node's layer-2 accumulator record (used by edge2)
    float* ab = &g_acc2[(size_t)n * 12];
    float4 z = make_float4(0.f, 0.f, 0.f, 0.f);
    reinterpret_cast<float4*>(ab)[0] = z;
    reinterpret_cast<float4*>(ab)[1] = z;
    ab[8] = 0.0f;
}

// ---------------------------------------------------------------------------
// 3) layer-2 edge pass (real edges only), 2 edges per thread:
//    w = exp(lrelu(als[s] + ald[d])); acc2[d] += {S: w, num[c]: w*h2[s][c]}
// ---------------------------------------------------------------------------
__device__ __forceinline__ void edge2_body(int s, int d) {
    uint4 raw = *reinterpret_cast<const uint4*>(g_n2[s].h2);
    __half2 pk[4];
    *reinterpret_cast<uint4*>(pk) = raw;
    float als = g_n2[s].als;
    float ald = __ldg(&g_ald[d]);

    float e = als + ald;
    e = (e > 0.0f) ? e : NEG * e;
    float w = __expf(e);

    float2 f0 = __half22float2(pk[0]);
    float2 f1 = __half22float2(pk[1]);
    float2 f2 = __half22float2(pk[2]);
    float2 f3 = __half22float2(pk[3]);

    float* ab = &g_acc2[(size_t)d * 12];
    red4(ab,     w,        w * f0.x, w * f0.y, w * f1.x);
    red4(ab + 4, w * f1.y, w * f2.x, w * f2.y, w * f3.x);
    atomicAdd(ab + 8, w * f3.y);
}

__global__ void __launch_bounds__(256) k_edge2(const int* __restrict__ src,
                                               const int* __restrict__ dst,
                                               int E) {
    int t = blockIdx.x * blockDim.x + threadIdx.x;
    int i0 = 2 * t;
    if (i0 >= E) return;
    if (i0 + 1 < E) {
        int2 ss = *reinterpret_cast<const int2*>(src + i0);
        int2 dd = *reinterpret_cast<const int2*>(dst + i0);
        edge2_body(ss.x, dd.x);
        edge2_body(ss.y, dd.y);
    } else {
        edge2_body(src[i0], dst[i0]);
    }
}

// ---------------------------------------------------------------------------
// 4) final: layer-2 self-loop analytically, normalize + bias -> out.
//    Also re-zeroes this node's g_acc1 record (restores invariant for the
//    next kernel_launch call — device globals start zeroed at load).
// ---------------------------------------------------------------------------
__global__ void __launch_bounds__(256) k_final(float* __restrict__ out,
                                               const float* __restrict__ b2) {
    __shared__ float sb2[8];
    int tid = threadIdx.x;
    if (tid < 8) sb2[tid] = b2[tid];
    __syncthreads();

    int n = blockIdx.x * blockDim.x + tid;
    if (n >= NN) return;

    const float* ab = &g_acc2[(size_t)n * 12];
    float S  = ab[0];
    float4 q0 = make_float4(ab[1], ab[2], ab[3], ab[4]);
    float4 q1 = make_float4(ab[5], ab[6], ab[7], ab[8]);

    // layer-2 self-loop from own record
    uint4 raw = *reinterpret_cast<const uint4*>(g_n2[n].h2);
    __half2 pk[4];
    *reinterpret_cast<uint4*>(pk) = raw;
    float als = g_n2[n].als;
    float ald = g_ald[n];

    float e = als + ald;
    e = (e > 0.0f) ? e : NEG * e;
    float w = __expf(e);

    float2 f0 = __half22float2(pk[0]);
    float2 f1 = __half22float2(pk[1]);
    float2 f2 = __half22float2(pk[2]);
    float2 f3 = __half22float2(pk[3]);

    float inv = 1.0f / (S + w);
    float4 o0 = make_float4((q0.x + w * f0.x) * inv + sb2[0],
                            (q0.y + w * f0.y) * inv + sb2[1],
                            (q0.z + w * f1.x) * inv + sb2[2],
                            (q0.w + w * f1.y) * inv + sb2[3]);
    float4 o1 = make_float4((q1.x + w * f2.x) * inv + sb2[4],
                            (q1.y + w * f2.y) * inv + sb2[5],
                            (q1.z + w * f3.x) * inv + sb2[6],
                            (q1.w + w * f3.y) * inv + sb2[7]);
    float4* ob = reinterpret_cast<float4*>(&out[(size_t)n * 8]);
    ob[0] = o0;
    ob[1] = o1;

    // restore zero invariant on layer-1 accumulator for the next call
    float4 z = make_float4(0.f, 0.f, 0.f, 0.f);
    float4* za = reinterpret_cast<float4*>(&g_acc1[(size_t)n * 8]);
    za[0] = z;
    za[1] = z;
}

extern "C" void kernel_launch(void* const* d_in, const int* in_sizes, int n_in,
                              void* d_out, int out_size) {
    const float* x   = (const float*)d_in[0];
    const int*   ei  = (const int*)d_in[1];
    const float* W1  = (const float*)d_in[2];
    const float* as1 = (const float*)d_in[3];
    const float* ad1 = (const float*)d_in[4];
    const float* b1  = (const float*)d_in[5];
    const float* W2  = (const float*)d_in[6];
    const float* as2 = (const float*)d_in[7];
    const float* ad2 = (const float*)d_in[8];
    const float* b2  = (const float*)d_in[9];
    float* out = (float*)d_out;

    int E = in_sizes[1] / 2;
    const int* src = ei;
    const int* dst = ei + E;

    int tb = 256;
    int eb2 = ((E + 1) / 2 + tb - 1) / tb;   // 2 edges per thread
    int nb = (NN + tb - 1) / tb;

    k_edge1<<<eb2, tb>>>(x, src, dst, W1, as1, ad1, E);
    k_mid<<<nb, tb>>>(x, W1, as1, ad1, b1, W2, as2, ad2);
    k_edge2<<<eb2, tb>>>(src, dst, E);
    k_final<<<nb, tb>>>(out, b2);
}

// round 16
// speedup vs baseline: 1.2913x; 1.0101x over previous
#include <cuda_runtime.h>
#include <cuda_fp16.h>

#define NN 100000
#define H1D 4
#define CD 8
#define NEG 0.2f

// Persistent device scratch (no allocations allowed in kernel_launch).
// Zero-initialized at module load; k_mid restores g_acc1's zero invariant
// after consuming it and lazily initializes g_acc2 each call.
__device__ float g_acc1[NN * 8];    // per node: S0,T0,S1,T1,S2,T2,S3,T3 (32B aligned)
__device__ float g_acc2[NN * 12];   // per node: S, num[0..7], pad x3

// Packed layer-2 source record: h2 fp16x8 (16B) + als fp32 => 20B in 32B record
struct __align__(32) Node2 {
    __half2 h2[4];
    float   als;
    float   pad[3];
};
__device__ Node2 g_n2[NN];
__device__ float g_ald[NN];         // dense read-only during edge2 (L1-cacheable)

__device__ __forceinline__ void red4(float* addr, float a, float b, float c, float d) {
    asm volatile("red.global.add.v4.f32 [%0], {%1, %2, %3, %4};"
                 :: "l"(addr), "f"(a), "f"(b), "f"(c), "f"(d) : "memory");
}

// Compute per-head logit scalars ws/wd into shared memory (threads 0..3).
__device__ __forceinline__ void prep_wswd(float* sws, float* swd,
                                          const float* __restrict__ W1,
                                          const float* __restrict__ as1,
                                          const float* __restrict__ ad1) {
    int tid = threadIdx.x;
    if (tid < H1D) {
        float s = 0.0f, d = 0.0f;
#pragma unroll
        for (int c = 0; c < CD; c++) {
            float w = W1[tid * CD + c];
            s += w * as1[tid * CD + c];
            d += w * ad1[tid * CD + c];
        }
        sws[tid] = s;
        swd[tid] = d;
    }
}

// ---------------------------------------------------------------------------
// 1) layer-1 edge pass (real edges only), 2 edges per thread (int2 indices):
//    per head: w = exp(lrelu(x_s*ws + x_d*wd)); acc1[dst] += {S_h: w, T_h: w*x_s}
// ---------------------------------------------------------------------------
__device__ __forceinline__ void edge1_body(const float* __restrict__ x,
                                           const float* sws, const float* swd,
                                           int s, int d) {
    float xs = __ldg(&x[s]);
    float xd = __ldg(&x[d]);
    float v[8];
#pragma unroll
    for (int h = 0; h < H1D; h++) {
        float e = xs * sws[h] + xd * swd[h];
        e = (e > 0.0f) ? e : NEG * e;
        float w = __expf(e);
        v[2 * h]     = w;
        v[2 * h + 1] = w * xs;
    }
    float* base = &g_acc1[(size_t)d * 8];
    red4(base,     v[0], v[1], v[2], v[3]);
    red4(base + 4, v[4], v[5], v[6], v[7]);
}

__global__ void __launch_bounds__(256) k_edge1(const float* __restrict__ x,
                                               const int* __restrict__ src,
                                               const int* __restrict__ dst,
                                               const float* __restrict__ W1,
                                               const float* __restrict__ as1,
                                               const float* __restrict__ ad1,
                                               int E) {
    __shared__ float sws[H1D], swd[H1D];
    prep_wswd(sws, swd, W1, as1, ad1);
    __syncthreads();

    int t = blockIdx.x * blockDim.x + threadIdx.x;
    int i0 = 2 * t;
    if (i0 >= E) return;
    if (i0 + 1 < E) {
        int2 ss = *reinterpret_cast<const int2*>(src + i0);
        int2 dd = *reinterpret_cast<const int2*>(dst + i0);
        edge1_body(x, sws, swd, ss.x, dd.x);
        edge1_body(x, sws, swd, ss.y, dd.y);
    } else {
        edge1_body(x, sws, swd, src[i0], dst[i0]);
    }
}

// ---------------------------------------------------------------------------
// 2) per-node: layer-1 self-loop + epilogue + relu + W2 GEMV + layer-2 logit
//    precompute. Writes packed source record + dense ald, zero-inits g_acc2,
//    and restores g_acc1's zero invariant (consumed this call, needed zeroed
//    at the start of the next call).
// ---------------------------------------------------------------------------
__global__ void __launch_bounds__(256) k_mid(const float* __restrict__ x,
                                             const float* __restrict__ W1,
                                             const float* __restrict__ as1,
                                             const float* __restrict__ ad1,
                                             const float* __restrict__ b1,
                                             const float* __restrict__ W2,
                                             const float* __restrict__ as2,
                                             const float* __restrict__ ad2) {
    __shared__ float sW2[32 * 8];
    __shared__ float sW1[32];
    __shared__ float sb1[32];
    __shared__ float sa[16];
    __shared__ float sws[H1D], swd[H1D];
    int tid = threadIdx.x;
    prep_wswd(sws, swd, W1, as1, ad1);
    if (tid < 256) sW2[tid] = W2[tid];
    if (tid < 32) { sW1[tid] = W1[tid]; sb1[tid] = b1[tid]; }
    if (tid < 8)  { sa[tid] = as2[tid]; sa[8 + tid] = ad2[tid]; }
    __syncthreads();

    int n = blockIdx.x * blockDim.x + tid;
    if (n >= NN) return;

    float4* a1 = reinterpret_cast<float4*>(&g_acc1[(size_t)n * 8]);
    float4 p0 = a1[0];  // S0,T0,S1,T1
    float4 p1 = a1[1];  // S2,T2,S3,T3

    // restore zero invariant for the next kernel_launch call
    float4 z = make_float4(0.f, 0.f, 0.f, 0.f);
    a1[0] = z;
    a1[1] = z;

    // layer-1 self-loop contribution (src = dst = n)
    float xd = __ldg(&x[n]);
    float Sv[H1D] = {p0.x, p0.z, p1.x, p1.z};
    float Tv[H1D] = {p0.y, p0.w, p1.y, p1.w};
#pragma unroll
    for (int h = 0; h < H1D; h++) {
        float e = xd * (sws[h] + swd[h]);
        e = (e > 0.0f) ? e : NEG * e;
        float w = __expf(e);
        Sv[h] += w;
        Tv[h] += w * xd;
    }

    float ts[H1D];
#pragma unroll
    for (int h = 0; h < H1D; h++) ts[h] = Tv[h] / Sv[h];

    float h2[CD];
#pragma unroll
    for (int c = 0; c < CD; c++) h2[c] = 0.0f;
#pragma unroll
    for (int hc = 0; hc < 32; hc++) {
        float r = sW1[hc] * ts[hc >> 3] + sb1[hc];
        r = fmaxf(r, 0.0f);
#pragma unroll
        for (int c = 0; c < CD; c++) h2[c] += r * sW2[hc * 8 + c];
    }
    float als = 0.0f, ald = 0.0f;
#pragma unroll
    for (int c = 0; c < CD; c++) {
        als += h2[c] * sa[c];
        ald += h2[c] * sa[8 + c];
    }

    // pack h2 -> fp16x8 (one 16B store) + als
    __half2 pk[4];
    pk[0] = __floats2half2_rn(h2[0], h2[1]);
    pk[1] = __floats2half2_rn(h2[2], h2[3]);
    pk[2] = __floats2half2_rn(h2[4], h2[5]);
    pk[3] = __floats2half2_rn(h2[6], h2[7]);
    *reinterpret_cast<uint4*>(g_n2[n].h2) = *reinterpret_cast<const uint4*>(pk);
    g_n2[n].als = als;
    g_ald[n] = ald;

    // lazy zero-init of this node's layer-2 accumulator record (used by edge2)
    float* ab = &g_acc2[(size_t)n * 12];
    reinterpret_cast<float4*>(ab)[0] = z;
    reinterpret_cast<float4*>(ab)[1] = z;
    ab[8] = 0.0f;
}

// ---------------------------------------------------------------------------
// 3) layer-2 edge pass (real edges only), 2 edges per thread:
//    w = exp(lrelu(als[s] + ald[d])); acc2[d] += {S: w, num[c]: w*h2[s][c]}
// ---------------------------------------------------------------------------
__device__ __forceinline__ void edge2_body(int s, int d) {
    uint4 raw = *reinterpret_cast<const uint4*>(g_n2[s].h2);
    __half2 pk[4];
    *reinterpret_cast<uint4*>(pk) = raw;
    float als = g_n2[s].als;
    float ald = __ldg(&g_ald[d]);

    float e = als + ald;
    e = (e > 0.0f) ? e : NEG * e;
    float w = __expf(e);

    float2 f0 = __half22float2(pk[0]);
    float2 f1 = __half22float2(pk[1]);
    float2 f2 = __half22float2(pk[2]);
    float2 f3 = __half22float2(pk[3]);

    float* ab = &g_acc2[(size_t)d * 12];
    red4(ab,     w,        w * f0.x, w * f0.y, w * f1.x);
    red4(ab + 4, w * f1.y, w * f2.x, w * f2.y, w * f3.x);
    atomicAdd(ab + 8, w * f3.y);
}

__global__ void __launch_bounds__(256) k_edge2(const int* __restrict__ src,
                                               const int* __restrict__ dst,
                                               int E) {
    int t = blockIdx.x * blockDim.x + threadIdx.x;
    int i0 = 2 * t;
    if (i0 >= E) return;
    if (i0 + 1 < E) {
        int2 ss = *reinterpret_cast<const int2*>(src + i0);
        int2 dd = *reinterpret_cast<const int2*>(dst + i0);
        edge2_body(ss.x, dd.x);
        edge2_body(ss.y, dd.y);
    } else {
        edge2_body(src[i0], dst[i0]);
    }
}

// ---------------------------------------------------------------------------
// 4) final: layer-2 self-loop analytically, normalize + bias -> out.
//    2 threads per node: each thread produces one float4 half of the output.
// ---------------------------------------------------------------------------
__global__ void __launch_bounds__(256) k_final(float* __restrict__ out,
                                               const float* __restrict__ b2) {
    __shared__ float sb2[8];
    int tid = threadIdx.x;
    if (tid < 8) sb2[tid] = b2[tid];
    __syncthreads();

    int t = blockIdx.x * blockDim.x + tid;
    int n = t >> 1;
    int half = t & 1;
    if (n >= NN) return;

    const float* ab = &g_acc2[(size_t)n * 12];
    float S = ab[0];
    const float* qb = ab + 1 + half * 4;
    float4 q = make_float4(qb[0], qb[1], qb[2], qb[3]);

    // this half's h2 channels (8B of packed fp16) + full logits
    const __half2* hp = g_n2[n].h2 + half * 2;
    __half2 pa = hp[0];
    __half2 pb = hp[1];
    float als = g_n2[n].als;
    float ald = g_ald[n];

    float e = als + ald;
    e = (e > 0.0f) ? e : NEG * e;
    float w = __expf(e);

    float2 fa = __half22float2(pa);
    float2 fb = __half22float2(pb);

    float inv = 1.0f / (S + w);
    const float* bb = &sb2[half * 4];
    float4 o = make_float4((q.x + w * fa.x) * inv + bb[0],
                           (q.y + w * fa.y) * inv + bb[1],
                           (q.z + w * fb.x) * inv + bb[2],
                           (q.w + w * fb.y) * inv + bb[3]);
    reinterpret_cast<float4*>(&out[(size_t)n * 8])[half] = o;
}

extern "C" void kernel_launch(void* const* d_in, const int* in_sizes, int n_in,
                              void* d_out, int out_size) {
    const float* x   = (const float*)d_in[0];
    const int*   ei  = (const int*)d_in[1];
    const float* W1  = (const float*)d_in[2];
    const float* as1 = (const float*)d_in[3];
    const float* ad1 = (const float*)d_in[4];
    const float* b1  = (const float*)d_in[5];
    const float* W2  = (const float*)d_in[6];
    const float* as2 = (const float*)d_in[7];
    const float* ad2 = (const float*)d_in[8];
    const float* b2  = (const float*)d_in[9];
    float* out = (float*)d_out;

    int E = in_sizes[1] / 2;
    const int* src = ei;
    const int* dst = ei + E;

    int tb = 256;
    int eb2 = ((E + 1) / 2 + tb - 1) / tb;   // 2 edges per thread
    int nb = (NN + tb - 1) / tb;
    int nb2 = (NN * 2 + tb - 1) / tb;        // 2 threads per node

    k_edge1<<<eb2, tb>>>(x, src, dst, W1, as1, ad1, E);
    k_mid<<<nb, tb>>>(x, W1, as1, ad1, b1, W2, as2, ad2);
    k_edge2<<<eb2, tb>>>(src, dst, E);
    k_final<<<nb2, tb>>>(out, b2);
}